// round 8
// baseline (speedup 1.0000x reference)
#include <cuda_runtime.h>

// ComposeTransform: out[b] = trilinear(disp1[b], grid + disp2[b]) + disp2[b]
// vol per batch: [D,H,W,3], D=160, H=192, W=160, batch=2.
// Warp-structured: each warp = 10 voxels, 30 active lanes (voxel,channel).
// d2 read with ONE coalesced LDG per lane + 2 shuffles (no smem, no barrier).
// Streaming store (__stcs) keeps L1 lines free for the 8-corner gathers.

#define DD 160
#define HH 192
#define WW 160
#define VOX (DD * HH * WW)
#define VPW 10                 // voxels per warp (30 active lanes)

__global__ __launch_bounds__(256, 7)
void compose_kernel(const float* __restrict__ d1,
                    const float* __restrict__ d2,
                    float* __restrict__ out)
{
    const int lane = threadIdx.x & 31;
    const int warp = (blockIdx.x * blockDim.x + threadIdx.x) >> 5;

    const int V = warp * VPW;            // first voxel of this warp
    const int t = 3 * V + lane;          // this lane's element index (lane<30)

    // one coalesced d2 load per lane (30 contiguous floats per warp)
    float e = 0.0f;
    if (lane < 30) e = __ldg(d2 + t);

    const int lv = lane / 3;             // local voxel 0..9 (garbage for 30,31)
    const int ch = lane - lv * 3;

    // assemble this voxel's displacement triplet via warp shuffle
    const int src = 3 * lv;
    float dx = __shfl_sync(0xffffffffu, e, src + 0);
    float dy = __shfl_sync(0xffffffffu, e, src + 1);
    float dz = __shfl_sync(0xffffffffu, e, src + 2);

    if (lane >= 30) return;

    const int v = V + lv;                // global voxel (includes batch)
    const int b = v / VOX;
    int r = v - b * VOX;
    int x = r / (HH * WW);
    int rem = r - x * (HH * WW);
    int y = rem / WW;
    int z = rem - y * WW;

    float lx = (float)x + dx;
    float ly = (float)y + dy;
    float lz = (float)z + dz;

    float fx = floorf(lx);
    float fy = floorf(ly);
    float fz = floorf(lz);

    // clipped floor / ceil corners (reference semantics)
    float i0x = fminf(fmaxf(fx, 0.0f), (float)(DD - 1));
    float i0y = fminf(fmaxf(fy, 0.0f), (float)(HH - 1));
    float i0z = fminf(fmaxf(fz, 0.0f), (float)(WW - 1));
    float i1x = fminf(fmaxf(fx + 1.0f, 0.0f), (float)(DD - 1));
    float i1y = fminf(fmaxf(fy + 1.0f, 0.0f), (float)(HH - 1));
    float i1z = fminf(fmaxf(fz + 1.0f, 0.0f), (float)(WW - 1));

    // weight attached to floor corner = clip(ceil_clipped - loc, 0, 1)
    float wfx = fminf(fmaxf(i1x - lx, 0.0f), 1.0f);
    float wfy = fminf(fmaxf(i1y - ly, 0.0f), 1.0f);
    float wfz = fminf(fmaxf(i1z - lz, 0.0f), 1.0f);
    float wcx = 1.0f - wfx;
    float wcy = 1.0f - wfy;
    float wcz = 1.0f - wfz;

    int ix0 = (int)i0x, iy0 = (int)i0y, iz0 = (int)i0z;
    int ix1 = (int)i1x, iy1 = (int)i1y, iz1 = (int)i1z;

    const float* vbase = d1 + (size_t)b * (size_t)(VOX * 3) + ch;

    int row00 = (ix0 * HH + iy0) * (WW * 3);
    int row01 = (ix0 * HH + iy1) * (WW * 3);
    int row10 = (ix1 * HH + iy0) * (WW * 3);
    int row11 = (ix1 * HH + iy1) * (WW * 3);
    int z0 = iz0 * 3;
    int z1 = iz1 * 3;

    float w00z0 = wfx * wfy * wfz;
    float w00z1 = wfx * wfy * wcz;
    float w01z0 = wfx * wcy * wfz;
    float w01z1 = wfx * wcy * wcz;
    float w10z0 = wcx * wfy * wfz;
    float w10z1 = wcx * wfy * wcz;
    float w11z0 = wcx * wcy * wfz;
    float w11z1 = wcx * wcy * wcz;

    float g0 = __ldg(vbase + (row00 + z0));
    float g1 = __ldg(vbase + (row00 + z1));
    float g2 = __ldg(vbase + (row01 + z0));
    float g3 = __ldg(vbase + (row01 + z1));
    float g4 = __ldg(vbase + (row10 + z0));
    float g5 = __ldg(vbase + (row10 + z1));
    float g6 = __ldg(vbase + (row11 + z0));
    float g7 = __ldg(vbase + (row11 + z1));

    float q0 = fmaf(w00z1, g1, w00z0 * g0);
    float q1 = fmaf(w01z1, g3, w01z0 * g2);
    float q2 = fmaf(w10z1, g5, w10z0 * g4);
    float q3 = fmaf(w11z1, g7, w11z0 * g6);
    float acc = (q0 + q1) + (q2 + q3);

    // e is exactly this element's d2 component; streaming store
    __stcs(out + t, acc + e);
}

extern "C" void kernel_launch(void* const* d_in, const int* in_sizes, int n_in,
                              void* d_out, int out_size) {
    const float* d1 = (const float*)d_in[0];
    const float* d2 = (const float*)d_in[1];
    float* out = (float*)d_out;
    // 9,830,400 voxels = 983,040 warps (10 voxels each) = 122,880 blocks of 8 warps
    int n_warps = (2 * VOX) / VPW;       // exact
    int blocks = n_warps / 8;            // 256 threads = 8 warps, exact
    compose_kernel<<<blocks, 256>>>(d1, d2, out);
}